// round 14
// baseline (speedup 1.0000x reference)
#include <cuda_runtime.h>
#include <cuda_fp16.h>
#include <math.h>
#include <stdint.h>

#define BSZ 16
#define CCH 512
#define NPIX 1024
#define NG 32

// Scratch (allocation-free rule => __device__ globals). All intermediates fp16.
__device__ __half g_h_h[(long)BSZ * CCH * NPIX];            // 16.8 MB
__device__ __half g_qkv_h[(long)BSZ * 3 * CCH * NPIX];      // 50 MB
__device__ __half g_attn_h[(long)BSZ * NPIX * NPIX];        // 33.5 MB (holds exp(scores))
__device__ __half g_o_h[(long)BSZ * CCH * NPIX];            // 16.8 MB
__device__ __half g_wh[(long)(3 * CCH + CCH) * CCH];        // 2 MB (qkv_w then out_w)
__device__ float  g_rs[(long)BSZ * NPIX];                   // row sums of exp(scores)

#define QKVW_ELEMS (3 * CCH * CCH)
#define OUTW_ELEMS (CCH * CCH)

// Converts weights to fp16 AND zeros the row-sum accumulators.
__global__ void convert_w_kernel(const float* __restrict__ qkv_w,
                                 const float* __restrict__ out_w) {
    int i = blockIdx.x * 256 + threadIdx.x;
    if (i < QKVW_ELEMS) g_wh[i] = __float2half(qkv_w[i]);
    else if (i < QKVW_ELEMS + OUTW_ELEMS) g_wh[i] = __float2half(out_w[i - QKVW_ELEMS]);
    if (i < BSZ * NPIX) g_rs[i] = 0.f;
}

// GroupNorm for batches [b0, b0+nb): grid = nb*NG blocks.
__global__ void groupnorm_kernel(const float* __restrict__ x,
                                 const float* __restrict__ w,
                                 const float* __restrict__ bb,
                                 int b0) {
    int blk = blockIdx.x;            // (b-b0)*NG + g
    int b = b0 + blk / NG, g = blk % NG;
    const int CPG = CCH / NG;        // 16
    const int LEN4 = CPG * NPIX / 4; // 4096 float4
    const float4* xp = (const float4*)(x + ((long)b * CCH + g * CPG) * NPIX);
    __half2* hp = (__half2*)(g_h_h + ((long)b * CCH + g * CPG) * NPIX);

    float s = 0.f, s2 = 0.f;
    for (int i = threadIdx.x; i < LEN4; i += blockDim.x) {
        float4 v = xp[i];
        s  += v.x + v.y + v.z + v.w;
        s2 += v.x * v.x + v.y * v.y + v.z * v.z + v.w * v.w;
    }
    __shared__ float sh_s[256], sh_s2[256];
    sh_s[threadIdx.x] = s; sh_s2[threadIdx.x] = s2;
    __syncthreads();
    for (int st = 128; st > 0; st >>= 1) {
        if (threadIdx.x < st) {
            sh_s[threadIdx.x]  += sh_s[threadIdx.x + st];
            sh_s2[threadIdx.x] += sh_s2[threadIdx.x + st];
        }
        __syncthreads();
    }
    const float LEN = (float)(CPG * NPIX);
    float mean = sh_s[0] / LEN;
    float var  = sh_s2[0] / LEN - mean * mean;
    float inv  = rsqrtf(var + 1e-5f);
    for (int i = threadIdx.x; i < LEN4; i += blockDim.x) {
        int c = g * CPG + (i >> 8);
        float sc = inv * w[c];
        float off = bb[c] - mean * sc;
        float4 v = xp[i];
        hp[2 * i]     = __floats2half2_rn(v.x * sc + off, v.y * sc + off);
        hp[2 * i + 1] = __floats2half2_rn(v.z * sc + off, v.w * sc + off);
    }
}

__device__ __forceinline__ void mma_f16(float* c,
                                        uint32_t a0, uint32_t a1, uint32_t a2, uint32_t a3,
                                        uint32_t b0, uint32_t b1) {
    asm volatile(
        "mma.sync.aligned.m16n8k16.row.col.f32.f16.f16.f32 "
        "{%0,%1,%2,%3}, {%4,%5,%6,%7}, {%8,%9}, {%0,%1,%2,%3};\n"
        : "+f"(c[0]), "+f"(c[1]), "+f"(c[2]), "+f"(c[3])
        : "r"(a0), "r"(a1), "r"(a2), "r"(a3), "r"(b0), "r"(b1));
}

__device__ __forceinline__ void ldsm4(uint32_t& r0, uint32_t& r1, uint32_t& r2, uint32_t& r3,
                                      uint32_t a) {
    asm volatile("ldmatrix.sync.aligned.m8n8.x4.shared.b16 {%0,%1,%2,%3}, [%4];"
                 : "=r"(r0), "=r"(r1), "=r"(r2), "=r"(r3) : "r"(a));
}
__device__ __forceinline__ void ldsm4t(uint32_t& r0, uint32_t& r1, uint32_t& r2, uint32_t& r3,
                                       uint32_t a) {
    asm volatile("ldmatrix.sync.aligned.m8n8.x4.trans.shared.b16 {%0,%1,%2,%3}, [%4];"
                 : "=r"(r0), "=r"(r1), "=r"(r2), "=r"(r3) : "r"(a));
}

__device__ __forceinline__ void cpa16(uint32_t saddr, const void* g) {
    asm volatile("cp.async.cg.shared.global [%0], [%1], 16;\n" :: "r"(saddr), "l"(g));
}
__device__ __forceinline__ void cp_commit() {
    asm volatile("cp.async.commit_group;\n");
}
__device__ __forceinline__ void cp_wait2() {
    asm volatile("cp.async.wait_group 2;\n");
}

// Block tile 128x128x16 (fp16 operands, fp32 accum), 256 threads, 8 warps each 64x32.
#define KROW 24
#define IROW 136
#define OP_HALVES 3072                  // max(128*24, 16*136=2176)
#define STG_HALVES (2 * OP_HALVES)      // 6144
#define NSTAGE 4
#define SMEM_BYTES (NSTAGE * STG_HALVES * 2)   // 49152 B

// C[b][i,j] = scale * sum_k A[i,k]*B[k,j] (+bias[i]) (+resid)
// EMODE: 0 none
//        1 expf before half store + atomicAdd per-row sums into rsum[b*sCs + i]
//        2 divide by cs[b*sCs + j]
template<bool AK1, bool BJ1, bool OUTF32, int EMODE>
__global__ __launch_bounds__(256, 2)
void tgemm_h(const __half* __restrict__ A, const __half* __restrict__ Bm,
             void* __restrict__ Cm,
             const float* __restrict__ bias, const float* __restrict__ resid,
             const float* __restrict__ cs, float* __restrict__ rsum, long sCs,
             int M, int Nn, int K,
             long sAi, long sAk, long sAb,
             long sBk, long sBj, long sBb,
             long sCb, long sRb, float scale) {
    extern __shared__ __half sm[];
    uint32_t smbase = (uint32_t)__cvta_generic_to_shared((void*)sm);

    const int b  = blockIdx.z;
    const int i0 = blockIdx.y * 128;
    const int j0 = blockIdx.x * 128;
    const __half* Ab = A + (long)b * sAb;
    const __half* Bb = Bm + (long)b * sBb;

    const int tid  = threadIdx.x;
    const int wid  = tid >> 5;
    const int lane = tid & 31;
    const int g    = lane >> 2;   // 0..7
    const int tl   = lane & 3;    // 0..3
    const int mWarp = (wid & 1) * 64;
    const int nWarp = (wid >> 1) * 32;

    const int KT = K >> 4;

    // cp.async: one 16B chunk per thread per operand per stage
    int a_row, a_off, b_row, b_off;
    if (AK1) { a_row = tid >> 1;  a_off = (tid & 1) * 8; }
    else     { a_row = tid >> 4;  a_off = (tid & 15) * 8; }
    if (BJ1) { b_row = tid >> 4;  b_off = (tid & 15) * 8; }
    else     { b_row = tid >> 1;  b_off = (tid & 1) * 8; }

    auto issue = [&](int ki) {
        if (ki < KT) {
            const int k0 = ki << 4;
            uint32_t abase = smbase + ((ki & (NSTAGE - 1)) * STG_HALVES) * 2;
            uint32_t bbase = abase + OP_HALVES * 2;
            const __half* gp;
            uint32_t sa;
            if (AK1) {
                gp = Ab + (long)(i0 + a_row) * sAi + (long)(k0 + a_off);
                sa = abase + (a_row * KROW + a_off) * 2;
            } else {
                gp = Ab + (long)(k0 + a_row) * sAk + (long)(i0 + a_off);
                sa = abase + (a_row * IROW + a_off) * 2;
            }
            cpa16(sa, gp);
            if (BJ1) {
                gp = Bb + (long)(k0 + b_row) * sBk + (long)(j0 + b_off);
                sa = bbase + (b_row * IROW + b_off) * 2;
            } else {
                gp = Bb + (long)(j0 + b_row) * sBj + (long)(k0 + b_off);
                sa = bbase + (b_row * KROW + b_off) * 2;
            }
            cpa16(sa, gp);
        }
        cp_commit();
    };

    // ldmatrix address offsets (bytes, relative to operand base within stage)
    uint32_t aoffs[4], boffs[2];
#pragma unroll
    for (int mt = 0; mt < 4; mt++) {
        const int m = mWarp + mt * 16;
        if (AK1) {
            int row = m + (lane & 7) + ((lane >> 3) & 1) * 8;
            int col = (lane >> 4) * 8;
            aoffs[mt] = (row * KROW + col) * 2;
        } else {
            int kr = ((lane >> 4) & 1) * 8 + (lane & 7);
            int mc = m + ((lane >> 3) & 1) * 8;
            aoffs[mt] = (kr * IROW + mc) * 2;
        }
    }
#pragma unroll
    for (int p = 0; p < 2; p++) {
        const int n = nWarp + p * 16;
        int mi = lane >> 3;
        if (BJ1) {
            int kr = (mi & 1) * 8 + (lane & 7);
            int nc = n + (mi >> 1) * 8;
            boffs[p] = (kr * IROW + nc) * 2;
        } else {
            int row = n + (mi >> 1) * 8 + (lane & 7);
            int col = (mi & 1) * 8;
            boffs[p] = (row * KROW + col) * 2;
        }
    }

    float c[4][4][4];
#pragma unroll
    for (int mt = 0; mt < 4; mt++)
#pragma unroll
        for (int nt = 0; nt < 4; nt++)
#pragma unroll
            for (int r = 0; r < 4; r++) c[mt][nt][r] = 0.f;

    issue(0); issue(1); issue(2);

    for (int i = 0; i < KT; i++) {
        cp_wait2();
        __syncthreads();
        issue(i + 3);

        uint32_t abase = smbase + ((i & (NSTAGE - 1)) * STG_HALVES) * 2;
        uint32_t bbase = abase + OP_HALVES * 2;

        uint32_t af[4][4];
#pragma unroll
        for (int mt = 0; mt < 4; mt++) {
            if (AK1) ldsm4(af[mt][0], af[mt][1], af[mt][2], af[mt][3], abase + aoffs[mt]);
            else     ldsm4t(af[mt][0], af[mt][1], af[mt][2], af[mt][3], abase + aoffs[mt]);
        }
        uint32_t bf[4][2];
#pragma unroll
        for (int p = 0; p < 2; p++) {
            uint32_t r0, r1, r2, r3;
            if (BJ1) ldsm4t(r0, r1, r2, r3, bbase + boffs[p]);
            else     ldsm4(r0, r1, r2, r3, bbase + boffs[p]);
            bf[2 * p][0] = r0; bf[2 * p][1] = r1;
            bf[2 * p + 1][0] = r2; bf[2 * p + 1][1] = r3;
        }
#pragma unroll
        for (int mt = 0; mt < 4; mt++)
#pragma unroll
            for (int nt = 0; nt < 4; nt++)
                mma_f16(c[mt][nt], af[mt][0], af[mt][1], af[mt][2], af[mt][3],
                        bf[nt][0], bf[nt][1]);
    }

    // epilogue
    const float* csb = (EMODE == 2) ? cs + (long)b * sCs : nullptr;
    float* rsb = (EMODE == 1) ? rsum + (long)b * sCs : nullptr;

    float inv[4][2];
    if (EMODE == 2) {
#pragma unroll
        for (int nt = 0; nt < 4; nt++) {
            int j = j0 + nWarp + nt * 8 + 2 * tl;
            inv[nt][0] = __fdividef(1.f, csb[j]);
            inv[nt][1] = __fdividef(1.f, csb[j + 1]);
        }
    }

#pragma unroll
    for (int mt = 0; mt < 4; mt++) {
        int r0 = i0 + mWarp + mt * 16 + g;
        int r1 = r0 + 8;
        float bv0 = bias ? bias[r0] : 0.f;
        float bv1 = bias ? bias[r1] : 0.f;
        float s0 = 0.f, s1 = 0.f;
#pragma unroll
        for (int nt = 0; nt < 4; nt++) {
            int j = j0 + nWarp + nt * 8 + 2 * tl;
            float v00 = c[mt][nt][0] * scale + bv0;
            float v01 = c[mt][nt][1] * scale + bv0;
            float v10 = c[mt][nt][2] * scale + bv1;
            float v11 = c[mt][nt][3] * scale + bv1;
            if (EMODE == 1) {
                v00 = __expf(v00); v01 = __expf(v01);
                v10 = __expf(v10); v11 = __expf(v11);
                s0 += v00 + v01;
                s1 += v10 + v11;
            }
            if (EMODE == 2) {
                v00 *= inv[nt][0]; v01 *= inv[nt][1];
                v10 *= inv[nt][0]; v11 *= inv[nt][1];
            }
            if (OUTF32) {
                float* Cb = (float*)Cm + (long)b * sCb;
                const float* Rb = resid + (long)b * sRb;
                const float2 q0 = *(const float2*)&Rb[(long)r0 * Nn + j];
                const float2 q1 = *(const float2*)&Rb[(long)r1 * Nn + j];
                float2 o0 = {v00 + q0.x, v01 + q0.y};
                float2 o1 = {v10 + q1.x, v11 + q1.y};
                *(float2*)&Cb[(long)r0 * Nn + j] = o0;
                *(float2*)&Cb[(long)r1 * Nn + j] = o1;
            } else {
                __half* Cb = (__half*)Cm + (long)b * sCb;
                *(__half2*)&Cb[(long)r0 * Nn + j] = __floats2half2_rn(v00, v01);
                *(__half2*)&Cb[(long)r1 * Nn + j] = __floats2half2_rn(v10, v11);
            }
        }
        if (EMODE == 1) {
            s0 += __shfl_xor_sync(0xFFFFFFFFu, s0, 1);
            s0 += __shfl_xor_sync(0xFFFFFFFFu, s0, 2);
            s1 += __shfl_xor_sync(0xFFFFFFFFu, s1, 1);
            s1 += __shfl_xor_sync(0xFFFFFFFFu, s1, 2);
            if (tl == 0) {
                atomicAdd(rsb + r0, s0);
                atomicAdd(rsb + r1, s1);
            }
        }
    }
}

#define NSPLIT 4

extern "C" void kernel_launch(void* const* d_in, const int* in_sizes, int n_in,
                              void* d_out, int out_size) {
    const float* x     = (const float*)d_in[0];
    const float* gn_w  = (const float*)d_in[1];
    const float* gn_b  = (const float*)d_in[2];
    const float* qkv_w = (const float*)d_in[3];
    const float* qkv_b = (const float*)d_in[4];
    const float* out_w = (const float*)d_in[5];
    const float* out_b = (const float*)d_in[6];
    float* out = (float*)d_out;

    __half *h, *qkv, *attn, *o, *wh;
    float* rs;
    cudaGetSymbolAddress((void**)&h, g_h_h);
    cudaGetSymbolAddress((void**)&qkv, g_qkv_h);
    cudaGetSymbolAddress((void**)&attn, g_attn_h);
    cudaGetSymbolAddress((void**)&o, g_o_h);
    cudaGetSymbolAddress((void**)&wh, g_wh);
    cudaGetSymbolAddress((void**)&rs, g_rs);

    static cudaStream_t sx[NSPLIT] = {};   // sx[0] stays null = default stream
    static cudaEvent_t e0 = nullptr;
    static cudaEvent_t ej[NSPLIT] = {};
    static bool init_done = false;
    if (!init_done) {
        cudaFuncSetAttribute(tgemm_h<true, true, false, 0>,
                             cudaFuncAttributeMaxDynamicSharedMemorySize, SMEM_BYTES);
        cudaFuncSetAttribute(tgemm_h<false, true, false, 1>,
                             cudaFuncAttributeMaxDynamicSharedMemorySize, SMEM_BYTES);
        cudaFuncSetAttribute(tgemm_h<true, false, false, 2>,
                             cudaFuncAttributeMaxDynamicSharedMemorySize, SMEM_BYTES);
        cudaFuncSetAttribute(tgemm_h<true, true, true, 0>,
                             cudaFuncAttributeMaxDynamicSharedMemorySize, SMEM_BYTES);
        for (int i = 1; i < NSPLIT; i++)
            cudaStreamCreateWithFlags(&sx[i], cudaStreamNonBlocking);
        cudaEventCreateWithFlags(&e0, cudaEventDisableTiming);
        for (int i = 1; i < NSPLIT; i++)
            cudaEventCreateWithFlags(&ej[i], cudaEventDisableTiming);
        init_done = true;
    }

    const long sH  = (long)CCH * NPIX;       // 512*1024
    const long sQ  = (long)3 * CCH * NPIX;   // 1536*1024
    const long sAt = (long)NPIX * NPIX;      // 1024*1024
    const int QB = BSZ / NSPLIT;             // 4 batches per stream

    // 0) Convert weights + zero row sums (stream 0); fan out to side streams.
    convert_w_kernel<<<(QKVW_ELEMS + OUTW_ELEMS + 255) / 256, 256>>>(qkv_w, out_w);
    cudaEventRecord(e0, 0);
    for (int i = 1; i < NSPLIT; i++) cudaStreamWaitEvent(sx[i], e0, 0);

    // Per-quarter chains: groupnorm -> QKV -> scores+exp -> A·V -> out-proj.
    for (int q = 0; q < NSPLIT; q++) {
        cudaStream_t st = sx[q];
        const long bo = (long)q * QB;
        const __half* hP   = h    + bo * sH;
        __half* qkvP       = qkv  + bo * sQ;
        __half* attnP      = attn + bo * sAt;
        __half* oP         = o    + bo * sH;
        float*  rsP        = rs   + bo * NPIX;
        const float* xP    = x    + bo * sH;
        float*  outP       = out  + bo * sH;

        groupnorm_kernel<<<QB * NG, 256, 0, st>>>(x, gn_w, gn_b, (int)bo);

        tgemm_h<true, true, false, 0><<<dim3(NPIX / 128, (3 * CCH) / 128, QB), 256, SMEM_BYTES, st>>>(
            wh, hP, qkvP, qkv_b, nullptr, nullptr, nullptr, 0,
            3 * CCH, NPIX, CCH,
            512, 1, 0,
            1024, 1, sH,
            sQ, 0, 1.0f);

        tgemm_h<false, true, false, 1><<<dim3(NPIX / 128, NPIX / 128, QB), 256, SMEM_BYTES, st>>>(
            qkvP, qkvP + (long)CCH * NPIX, attnP, nullptr, nullptr, nullptr, rsP, (long)NPIX,
            NPIX, NPIX, CCH,
            1, 1024, sQ,
            1024, 1, sQ,
            sAt, 0, 1.0f / sqrtf((float)CCH));

        tgemm_h<true, false, false, 2><<<dim3(NPIX / 128, CCH / 128, QB), 256, SMEM_BYTES, st>>>(
            qkvP + 2L * CCH * NPIX, attnP, oP, nullptr, nullptr, rsP, nullptr, (long)NPIX,
            CCH, NPIX, NPIX,
            1024, 1, sQ,
            1, 1024, sAt,
            sH, 0, 1.0f);

        tgemm_h<true, true, true, 0><<<dim3(NPIX / 128, CCH / 128, QB), 256, SMEM_BYTES, st>>>(
            wh + QKVW_ELEMS, oP, outP, out_b, xP, nullptr, nullptr, 0,
            CCH, NPIX, CCH,
            512, 1, 0,
            1024, 1, sH,
            sH, sH, 1.0f);
    }

    // Join all side streams back into the default stream.
    for (int i = 1; i < NSPLIT; i++) {
        cudaEventRecord(ej[i], sx[i]);
        cudaStreamWaitEvent(0, ej[i], 0);
    }
}

// round 16
// speedup vs baseline: 1.0146x; 1.0146x over previous
#include <cuda_runtime.h>
#include <cuda_fp16.h>
#include <math.h>
#include <stdint.h>

#define BSZ 16
#define CCH 512
#define NPIX 1024
#define NG 32

// Scratch (allocation-free rule => __device__ globals). All intermediates fp16.
__device__ __half g_h_h[(long)BSZ * CCH * NPIX];            // 16.8 MB
__device__ __half g_qkv_h[(long)BSZ * 3 * CCH * NPIX];      // 50 MB
__device__ __half g_attn_h[(long)BSZ * NPIX * NPIX];        // 33.5 MB (holds exp(scores))
__device__ __half g_o_h[(long)BSZ * CCH * NPIX];            // 16.8 MB
__device__ __half g_wh[(long)(3 * CCH + CCH) * CCH];        // 2 MB (qkv_w then out_w)
__device__ float  g_rs[(long)BSZ * NPIX];                   // row sums of exp(scores)

#define QKVW_ELEMS (3 * CCH * CCH)
#define OUTW_ELEMS (CCH * CCH)

// Converts weights to fp16 AND zeros the row-sum accumulators.
__global__ void convert_w_kernel(const float* __restrict__ qkv_w,
                                 const float* __restrict__ out_w) {
    int i = blockIdx.x * 256 + threadIdx.x;
    if (i < QKVW_ELEMS) g_wh[i] = __float2half(qkv_w[i]);
    else if (i < QKVW_ELEMS + OUTW_ELEMS) g_wh[i] = __float2half(out_w[i - QKVW_ELEMS]);
    if (i < BSZ * NPIX) g_rs[i] = 0.f;
}

// GroupNorm for batches [b0, b0+nb): grid = nb*NG blocks.
__global__ void groupnorm_kernel(const float* __restrict__ x,
                                 const float* __restrict__ w,
                                 const float* __restrict__ bb,
                                 int b0) {
    int blk = blockIdx.x;            // (b-b0)*NG + g
    int b = b0 + blk / NG, g = blk % NG;
    const int CPG = CCH / NG;        // 16
    const int LEN4 = CPG * NPIX / 4; // 4096 float4
    const float4* xp = (const float4*)(x + ((long)b * CCH + g * CPG) * NPIX);
    __half2* hp = (__half2*)(g_h_h + ((long)b * CCH + g * CPG) * NPIX);

    float s = 0.f, s2 = 0.f;
    for (int i = threadIdx.x; i < LEN4; i += blockDim.x) {
        float4 v = xp[i];
        s  += v.x + v.y + v.z + v.w;
        s2 += v.x * v.x + v.y * v.y + v.z * v.z + v.w * v.w;
    }
    __shared__ float sh_s[256], sh_s2[256];
    sh_s[threadIdx.x] = s; sh_s2[threadIdx.x] = s2;
    __syncthreads();
    for (int st = 128; st > 0; st >>= 1) {
        if (threadIdx.x < st) {
            sh_s[threadIdx.x]  += sh_s[threadIdx.x + st];
            sh_s2[threadIdx.x] += sh_s2[threadIdx.x + st];
        }
        __syncthreads();
    }
    const float LEN = (float)(CPG * NPIX);
    float mean = sh_s[0] / LEN;
    float var  = sh_s2[0] / LEN - mean * mean;
    float inv  = rsqrtf(var + 1e-5f);
    for (int i = threadIdx.x; i < LEN4; i += blockDim.x) {
        int c = g * CPG + (i >> 8);
        float sc = inv * w[c];
        float off = bb[c] - mean * sc;
        float4 v = xp[i];
        hp[2 * i]     = __floats2half2_rn(v.x * sc + off, v.y * sc + off);
        hp[2 * i + 1] = __floats2half2_rn(v.z * sc + off, v.w * sc + off);
    }
}

__device__ __forceinline__ void mma_f16(float* c,
                                        uint32_t a0, uint32_t a1, uint32_t a2, uint32_t a3,
                                        uint32_t b0, uint32_t b1) {
    asm volatile(
        "mma.sync.aligned.m16n8k16.row.col.f32.f16.f16.f32 "
        "{%0,%1,%2,%3}, {%4,%5,%6,%7}, {%8,%9}, {%0,%1,%2,%3};\n"
        : "+f"(c[0]), "+f"(c[1]), "+f"(c[2]), "+f"(c[3])
        : "r"(a0), "r"(a1), "r"(a2), "r"(a3), "r"(b0), "r"(b1));
}

__device__ __forceinline__ void ldsm4(uint32_t& r0, uint32_t& r1, uint32_t& r2, uint32_t& r3,
                                      uint32_t a) {
    asm volatile("ldmatrix.sync.aligned.m8n8.x4.shared.b16 {%0,%1,%2,%3}, [%4];"
                 : "=r"(r0), "=r"(r1), "=r"(r2), "=r"(r3) : "r"(a));
}
__device__ __forceinline__ void ldsm4t(uint32_t& r0, uint32_t& r1, uint32_t& r2, uint32_t& r3,
                                       uint32_t a) {
    asm volatile("ldmatrix.sync.aligned.m8n8.x4.trans.shared.b16 {%0,%1,%2,%3}, [%4];"
                 : "=r"(r0), "=r"(r1), "=r"(r2), "=r"(r3) : "r"(a));
}

__device__ __forceinline__ void cpa16(uint32_t saddr, const void* g) {
    asm volatile("cp.async.cg.shared.global [%0], [%1], 16;\n" :: "r"(saddr), "l"(g));
}
__device__ __forceinline__ void cp_commit() {
    asm volatile("cp.async.commit_group;\n");
}
__device__ __forceinline__ void cp_wait2() {
    asm volatile("cp.async.wait_group 2;\n");
}

// Block tile 128x128x16 (fp16 operands, fp32 accum), 256 threads, 8 warps each 64x32.
#define KROW 24
#define IROW 136
#define OP_HALVES 3072                  // max(128*24, 16*136=2176)
#define STG_HALVES (2 * OP_HALVES)      // 6144
#define NSTAGE 4
#define SMEM_BYTES (NSTAGE * STG_HALVES * 2)   // 49152 B

// C[b][i,j] = scale * sum_k A[i,k]*B[k,j] (+bias[i]) (+resid)
// EMODE: 0 none
//        1 expf before half store + atomicAdd per-row sums into rsum[b*sCs + i]
//        2 divide by cs[b*sCs + j]
template<bool AK1, bool BJ1, bool OUTF32, int EMODE>
__global__ __launch_bounds__(256, 2)
void tgemm_h(const __half* __restrict__ A, const __half* __restrict__ Bm,
             void* __restrict__ Cm,
             const float* __restrict__ bias, const float* __restrict__ resid,
             const float* __restrict__ cs, float* __restrict__ rsum, long sCs,
             int M, int Nn, int K,
             long sAi, long sAk, long sAb,
             long sBk, long sBj, long sBb,
             long sCb, long sRb, float scale) {
    extern __shared__ __half sm[];
    uint32_t smbase = (uint32_t)__cvta_generic_to_shared((void*)sm);

    const int b  = blockIdx.z;
    const int i0 = blockIdx.y * 128;
    const int j0 = blockIdx.x * 128;
    const __half* Ab = A + (long)b * sAb;
    const __half* Bb = Bm + (long)b * sBb;

    const int tid  = threadIdx.x;
    const int wid  = tid >> 5;
    const int lane = tid & 31;
    const int g    = lane >> 2;   // 0..7
    const int tl   = lane & 3;    // 0..3
    const int mWarp = (wid & 1) * 64;
    const int nWarp = (wid >> 1) * 32;

    const int KT = K >> 4;

    // cp.async: one 16B chunk per thread per operand per stage
    int a_row, a_off, b_row, b_off;
    if (AK1) { a_row = tid >> 1;  a_off = (tid & 1) * 8; }
    else     { a_row = tid >> 4;  a_off = (tid & 15) * 8; }
    if (BJ1) { b_row = tid >> 4;  b_off = (tid & 15) * 8; }
    else     { b_row = tid >> 1;  b_off = (tid & 1) * 8; }

    auto issue = [&](int ki) {
        if (ki < KT) {
            const int k0 = ki << 4;
            uint32_t abase = smbase + ((ki & (NSTAGE - 1)) * STG_HALVES) * 2;
            uint32_t bbase = abase + OP_HALVES * 2;
            const __half* gp;
            uint32_t sa;
            if (AK1) {
                gp = Ab + (long)(i0 + a_row) * sAi + (long)(k0 + a_off);
                sa = abase + (a_row * KROW + a_off) * 2;
            } else {
                gp = Ab + (long)(k0 + a_row) * sAk + (long)(i0 + a_off);
                sa = abase + (a_row * IROW + a_off) * 2;
            }
            cpa16(sa, gp);
            if (BJ1) {
                gp = Bb + (long)(k0 + b_row) * sBk + (long)(j0 + b_off);
                sa = bbase + (b_row * IROW + b_off) * 2;
            } else {
                gp = Bb + (long)(j0 + b_row) * sBj + (long)(k0 + b_off);
                sa = bbase + (b_row * KROW + b_off) * 2;
            }
            cpa16(sa, gp);
        }
        cp_commit();
    };

    // ldmatrix address offsets (bytes, relative to operand base within stage)
    uint32_t aoffs[4], boffs[2];
#pragma unroll
    for (int mt = 0; mt < 4; mt++) {
        const int m = mWarp + mt * 16;
        if (AK1) {
            int row = m + (lane & 7) + ((lane >> 3) & 1) * 8;
            int col = (lane >> 4) * 8;
            aoffs[mt] = (row * KROW + col) * 2;
        } else {
            int kr = ((lane >> 4) & 1) * 8 + (lane & 7);
            int mc = m + ((lane >> 3) & 1) * 8;
            aoffs[mt] = (kr * IROW + mc) * 2;
        }
    }
#pragma unroll
    for (int p = 0; p < 2; p++) {
        const int n = nWarp + p * 16;
        int mi = lane >> 3;
        if (BJ1) {
            int kr = (mi & 1) * 8 + (lane & 7);
            int nc = n + (mi >> 1) * 8;
            boffs[p] = (kr * IROW + nc) * 2;
        } else {
            int row = n + (mi >> 1) * 8 + (lane & 7);
            int col = (mi & 1) * 8;
            boffs[p] = (row * KROW + col) * 2;
        }
    }

    float c[4][4][4];
#pragma unroll
    for (int mt = 0; mt < 4; mt++)
#pragma unroll
        for (int nt = 0; nt < 4; nt++)
#pragma unroll
            for (int r = 0; r < 4; r++) c[mt][nt][r] = 0.f;

    issue(0); issue(1); issue(2);

    for (int i = 0; i < KT; i++) {
        cp_wait2();
        __syncthreads();
        issue(i + 3);

        uint32_t abase = smbase + ((i & (NSTAGE - 1)) * STG_HALVES) * 2;
        uint32_t bbase = abase + OP_HALVES * 2;

        uint32_t af[4][4];
#pragma unroll
        for (int mt = 0; mt < 4; mt++) {
            if (AK1) ldsm4(af[mt][0], af[mt][1], af[mt][2], af[mt][3], abase + aoffs[mt]);
            else     ldsm4t(af[mt][0], af[mt][1], af[mt][2], af[mt][3], abase + aoffs[mt]);
        }
        uint32_t bf[4][2];
#pragma unroll
        for (int p = 0; p < 2; p++) {
            uint32_t r0, r1, r2, r3;
            if (BJ1) ldsm4t(r0, r1, r2, r3, bbase + boffs[p]);
            else     ldsm4(r0, r1, r2, r3, bbase + boffs[p]);
            bf[2 * p][0] = r0; bf[2 * p][1] = r1;
            bf[2 * p + 1][0] = r2; bf[2 * p + 1][1] = r3;
        }
#pragma unroll
        for (int mt = 0; mt < 4; mt++)
#pragma unroll
            for (int nt = 0; nt < 4; nt++)
                mma_f16(c[mt][nt], af[mt][0], af[mt][1], af[mt][2], af[mt][3],
                        bf[nt][0], bf[nt][1]);
    }

    // epilogue
    const float* csb = (EMODE == 2) ? cs + (long)b * sCs : nullptr;
    float* rsb = (EMODE == 1) ? rsum + (long)b * sCs : nullptr;

    float inv[4][2];
    if (EMODE == 2) {
#pragma unroll
        for (int nt = 0; nt < 4; nt++) {
            int j = j0 + nWarp + nt * 8 + 2 * tl;
            inv[nt][0] = __fdividef(1.f, csb[j]);
            inv[nt][1] = __fdividef(1.f, csb[j + 1]);
        }
    }

#pragma unroll
    for (int mt = 0; mt < 4; mt++) {
        int r0 = i0 + mWarp + mt * 16 + g;
        int r1 = r0 + 8;
        float bv0 = bias ? bias[r0] : 0.f;
        float bv1 = bias ? bias[r1] : 0.f;
        float s0 = 0.f, s1 = 0.f;
#pragma unroll
        for (int nt = 0; nt < 4; nt++) {
            int j = j0 + nWarp + nt * 8 + 2 * tl;
            float v00 = c[mt][nt][0] * scale + bv0;
            float v01 = c[mt][nt][1] * scale + bv0;
            float v10 = c[mt][nt][2] * scale + bv1;
            float v11 = c[mt][nt][3] * scale + bv1;
            if (EMODE == 1) {
                v00 = __expf(v00); v01 = __expf(v01);
                v10 = __expf(v10); v11 = __expf(v11);
                s0 += v00 + v01;
                s1 += v10 + v11;
            }
            if (EMODE == 2) {
                v00 *= inv[nt][0]; v01 *= inv[nt][1];
                v10 *= inv[nt][0]; v11 *= inv[nt][1];
            }
            if (OUTF32) {
                float* Cb = (float*)Cm + (long)b * sCb;
                const float* Rb = resid + (long)b * sRb;
                const float2 q0 = *(const float2*)&Rb[(long)r0 * Nn + j];
                const float2 q1 = *(const float2*)&Rb[(long)r1 * Nn + j];
                float2 o0 = {v00 + q0.x, v01 + q0.y};
                float2 o1 = {v10 + q1.x, v11 + q1.y};
                *(float2*)&Cb[(long)r0 * Nn + j] = o0;
                *(float2*)&Cb[(long)r1 * Nn + j] = o1;
            } else {
                __half* Cb = (__half*)Cm + (long)b * sCb;
                *(__half2*)&Cb[(long)r0 * Nn + j] = __floats2half2_rn(v00, v01);
                *(__half2*)&Cb[(long)r1 * Nn + j] = __floats2half2_rn(v10, v11);
            }
        }
        if (EMODE == 1) {
            s0 += __shfl_xor_sync(0xFFFFFFFFu, s0, 1);
            s0 += __shfl_xor_sync(0xFFFFFFFFu, s0, 2);
            s1 += __shfl_xor_sync(0xFFFFFFFFu, s1, 1);
            s1 += __shfl_xor_sync(0xFFFFFFFFu, s1, 2);
            if (tl == 0) {
                atomicAdd(rsb + r0, s0);
                atomicAdd(rsb + r1, s1);
            }
        }
    }
}

extern "C" void kernel_launch(void* const* d_in, const int* in_sizes, int n_in,
                              void* d_out, int out_size) {
    const float* x     = (const float*)d_in[0];
    const float* gn_w  = (const float*)d_in[1];
    const float* gn_b  = (const float*)d_in[2];
    const float* qkv_w = (const float*)d_in[3];
    const float* qkv_b = (const float*)d_in[4];
    const float* out_w = (const float*)d_in[5];
    const float* out_b = (const float*)d_in[6];
    float* out = (float*)d_out;

    __half *h, *qkv, *attn, *o, *wh;
    float* rs;
    cudaGetSymbolAddress((void**)&h, g_h_h);
    cudaGetSymbolAddress((void**)&qkv, g_qkv_h);
    cudaGetSymbolAddress((void**)&attn, g_attn_h);
    cudaGetSymbolAddress((void**)&o, g_o_h);
    cudaGetSymbolAddress((void**)&wh, g_wh);
    cudaGetSymbolAddress((void**)&rs, g_rs);

    static cudaStream_t s2 = nullptr;
    static cudaEvent_t e_start = nullptr, e_cv = nullptr, e1 = nullptr;
    static bool init_done = false;
    if (!init_done) {
        cudaFuncSetAttribute(tgemm_h<true, true, false, 0>,
                             cudaFuncAttributeMaxDynamicSharedMemorySize, SMEM_BYTES);
        cudaFuncSetAttribute(tgemm_h<false, true, false, 1>,
                             cudaFuncAttributeMaxDynamicSharedMemorySize, SMEM_BYTES);
        cudaFuncSetAttribute(tgemm_h<true, false, false, 2>,
                             cudaFuncAttributeMaxDynamicSharedMemorySize, SMEM_BYTES);
        cudaFuncSetAttribute(tgemm_h<true, true, true, 0>,
                             cudaFuncAttributeMaxDynamicSharedMemorySize, SMEM_BYTES);
        cudaStreamCreateWithFlags(&s2, cudaStreamNonBlocking);
        cudaEventCreateWithFlags(&e_start, cudaEventDisableTiming);
        cudaEventCreateWithFlags(&e_cv, cudaEventDisableTiming);
        cudaEventCreateWithFlags(&e1, cudaEventDisableTiming);
        init_done = true;
    }

    const long sH  = (long)CCH * NPIX;       // 512*1024
    const long sQ  = (long)3 * CCH * NPIX;   // 1536*1024
    const long sAt = (long)NPIX * NPIX;      // 1024*1024
    const int HB = BSZ / 2;                  // 8 batches per stream

    // Fork FIRST (capture-legal: side stream joins by waiting on an origin-stream event),
    // then run the two prologue pieces concurrently:
    //   s0: groupnorm half0 (needs only x)
    //   s2: convert weights + zero rs, then groupnorm half1
    cudaEventRecord(e_start, 0);
    cudaStreamWaitEvent(s2, e_start, 0);

    groupnorm_kernel<<<HB * NG, 256>>>(x, gn_w, gn_b, 0);            // stream 0, batches 0..7
    convert_w_kernel<<<(QKVW_ELEMS + OUTW_ELEMS + 255) / 256, 256, 0, s2>>>(qkv_w, out_w);
    cudaEventRecord(e_cv, s2);
    groupnorm_kernel<<<HB * NG, 256, 0, s2>>>(x, gn_w, gn_b, HB);    // s2, batches 8..15

    // Chain 0 (stream 0) must also see the converted weights.
    cudaStreamWaitEvent(0, e_cv, 0);

    // Per-half chain. half=0 -> default stream, batches [0,8); half=1 -> s2, batches [8,16).
    for (int half = 0; half < 2; half++) {
        cudaStream_t st = half ? s2 : (cudaStream_t)0;
        const long bo = (long)half * HB;
        const __half* hP   = h    + bo * sH;
        __half* qkvP       = qkv  + bo * sQ;
        __half* attnP      = attn + bo * sAt;
        __half* oP         = o    + bo * sH;
        float*  rsP        = rs   + bo * NPIX;
        const float* xP    = x    + bo * sH;
        float*  outP       = out  + bo * sH;

        // QKV (fused 1536 rows)
        tgemm_h<true, true, false, 0><<<dim3(NPIX / 128, (3 * CCH) / 128, HB), 256, SMEM_BYTES, st>>>(
            wh, hP, qkvP, qkv_b, nullptr, nullptr, nullptr, 0,
            3 * CCH, NPIX, CCH,
            512, 1, 0,
            1024, 1, sH,
            sQ, 0, 1.0f);

        // scores -> exp -> attn, row sums via atomics
        tgemm_h<false, true, false, 1><<<dim3(NPIX / 128, NPIX / 128, HB), 256, SMEM_BYTES, st>>>(
            qkvP, qkvP + (long)CCH * NPIX, attnP, nullptr, nullptr, nullptr, rsP, (long)NPIX,
            NPIX, NPIX, CCH,
            1, 1024, sQ,
            1024, 1, sQ,
            sAt, 0, 1.0f / sqrtf((float)CCH));

        // A·V with 1/rowsum in epilogue
        tgemm_h<true, false, false, 2><<<dim3(NPIX / 128, CCH / 128, HB), 256, SMEM_BYTES, st>>>(
            qkvP + 2L * CCH * NPIX, attnP, oP, nullptr, nullptr, rsP, nullptr, (long)NPIX,
            CCH, NPIX, NPIX,
            1024, 1, sQ,
            1, 1024, sAt,
            sH, 0, 1.0f);

        // out-proj + residual -> fp32 out
        tgemm_h<true, true, true, 0><<<dim3(NPIX / 128, CCH / 128, HB), 256, SMEM_BYTES, st>>>(
            wh + QKVW_ELEMS, oP, outP, out_b, xP, nullptr, nullptr, 0,
            CCH, NPIX, CCH,
            512, 1, 0,
            1024, 1, sH,
            sH, sH, 1.0f);
    }

    // Join: s2's chain must complete before the capture's end node.
    cudaEventRecord(e1, s2);
    cudaStreamWaitEvent(0, e1, 0);
}